// round 15
// baseline (speedup 1.0000x reference)
#include <cuda_runtime.h>

// ------- scratch: 3 x 64MB = 192MB; referenced ONLY from device code ------
static __device__ float bA[16777216];   // z0 | z1 (stage D outputs)
static __device__ float bB[16777216];   // d (stage C/D)
static __device__ float bP[16777216];   // p0|p1 (stage D), then p0b|p1b (stage E)

// ---------------- filters (scalar + packed-pair tables) -------------------
__constant__ float c_h[9] = {
     0.037828455506995f, -0.02384946501938f, -0.11062440441842f,
     0.37740285561265f,   0.8526986790094f,   0.37740285561265f,
    -0.11062440441842f,  -0.02384946501938f,  0.037828455506995f };
__constant__ float c_g[7] = {
    -0.064538882628938f, -0.040689417609558f, 0.41809227322221f,
     0.78848561640566f,   0.41809227322221f, -0.040689417609558f,
    -0.064538882628938f };
__constant__ float c_f[12] = {
     0.0144f,  0.0272f,  0.0526f,  0.0972f,  0.193f,  0.63f,
    -0.63f,   -0.193f,  -0.0972f, -0.0526f, -0.0272f, -0.0144f };
__constant__ float2 c_h2[9] = {
    {0.037828455506995f,0.037828455506995f}, {-0.02384946501938f,-0.02384946501938f},
    {-0.11062440441842f,-0.11062440441842f}, {0.37740285561265f,0.37740285561265f},
    {0.8526986790094f,0.8526986790094f},     {0.37740285561265f,0.37740285561265f},
    {-0.11062440441842f,-0.11062440441842f}, {-0.02384946501938f,-0.02384946501938f},
    {0.037828455506995f,0.037828455506995f} };
__constant__ float2 c_g2[7] = {
    {-0.064538882628938f,-0.064538882628938f}, {-0.040689417609558f,-0.040689417609558f},
    {0.41809227322221f,0.41809227322221f},     {0.78848561640566f,0.78848561640566f},
    {0.41809227322221f,0.41809227322221f},     {-0.040689417609558f,-0.040689417609558f},
    {-0.064538882628938f,-0.064538882628938f} };
__constant__ float2 c_f2[12] = {
    {0.0144f,0.0144f},  {0.0272f,0.0272f},  {0.0526f,0.0526f},  {0.0972f,0.0972f},
    {0.193f,0.193f},    {0.63f,0.63f},      {-0.63f,-0.63f},    {-0.193f,-0.193f},
    {-0.0972f,-0.0972f},{-0.0526f,-0.0526f},{-0.0272f,-0.0272f},{-0.0144f,-0.0144f} };

#define INV_SQ2 0.7071067811865476f
#define SQ2     1.4142135623730951f
#define SEG     4194304L
#define HM 8388608

// packed dual-FMA: two independent IEEE rn fmas -> bit-identical to fmaf x2
__device__ __forceinline__ float2 f2fmap(float2 c, float2 v, float2 a) {
    unsigned long long au = *(unsigned long long*)&a;
    unsigned long long cu = *(unsigned long long*)&c;
    unsigned long long vu = *(unsigned long long*)&v;
    asm("fma.rn.f32x2 %0, %1, %2, %0;" : "+l"(au) : "l"(cu), "l"(vu));
    float2 r; *(unsigned long long*)&r = au; return r;
}
__device__ __forceinline__ float4 f4fmap(float2 c, float4 v, float4 a) {
    float2 lo = f2fmap(c, make_float2(v.x, v.y), make_float2(a.x, a.y));
    float2 hi = f2fmap(c, make_float2(v.z, v.w), make_float2(a.z, a.w));
    return make_float4(lo.x, lo.y, hi.x, hi.y);
}

// ===== K_AB: fused vh(stride2) + hh(stride2). x -> out seg0 (c) ===========
__global__ void __launch_bounds__(256) k_AB(const float* __restrict__ x,
                                            float* __restrict__ outc) {
    __shared__ float4 t[2048];          // 32 rows x 64 f4
    int rb = blockIdx.x & 3, img = blockIdx.x >> 2;
    int tid = threadIdx.x;
    const float4* xi = (const float4*)x + ((long)img << 14);
    {
        int jb = tid & 63, ib = tid >> 6;
        for (int rr = ib; rr < 32; rr += 4) {
            int i2 = rb * 32 + rr;
            float4 s = {0.f, 0.f, 0.f, 0.f};
#pragma unroll
            for (int k = 0; k < 9; ++k)
                s = f4fmap(c_h2[k], xi[(((2 * i2 + k - 4) & 255) << 6) + jb], s);
            t[rr * 64 + jb] = s;
        }
    }
    __syncthreads();
    {
        int jb = tid & 31, ib = tid >> 5;
        for (int rr = ib; rr < 32; rr += 8) {
            const float4* trow = t + rr * 64;
            float o0 = 0.f, o1 = 0.f, o2 = 0.f, o3 = 0.f;
#pragma unroll
            for (int s = 0; s < 5; ++s) {
                float4 v = trow[(2 * jb - 2 + s + 64) & 63];
                float vv[4] = {v.x, v.y, v.z, v.w};
#pragma unroll
                for (int u = 0; u < 4; ++u) {
                    int q = 4 * s + u;   // window idx; tap k = q - 2m - 4
                    int k0 = q - 4;
                    if (k0 >= 0 && k0 < 9) o0 = fmaf(c_h[k0], vv[u], o0);
                    int k1 = q - 6;
                    if (k1 >= 0 && k1 < 9) o1 = fmaf(c_h[k1], vv[u], o1);
                    int k2 = q - 8;
                    if (k2 >= 0 && k2 < 9) o2 = fmaf(c_h[k2], vv[u], o2);
                    int k3 = q - 10;
                    if (k3 >= 0 && k3 < 9) o3 = fmaf(c_h[k3], vv[u], o3);
                }
            }
            int i = rb * 32 + rr;
            ((float4*)outc)[((long)img << 12) + (i << 5) + jb] =
                make_float4(o0, o1, o2, o3);
        }
    }
}

// ===== K_C: fused (upsample+vert g) + (horiz g + sub). c,x -> bB = d ======
__global__ void __launch_bounds__(256) k_C(const float* __restrict__ cc,
                                           const float* __restrict__ x) {
    __shared__ float v[4096];           // 32 rows x 128 evencols
    int rb = blockIdx.x & 7, img = blockIdx.x >> 3;
    int tid = threadIdx.x;
    const float4* ci = (const float4*)cc + ((long)img << 12);
    {
        int jb = tid & 31, ib = tid >> 5;
        for (int rr = ib; rr < 32; rr += 8) {
            int i = rb * 32 + rr;
            float4 s = {0.f, 0.f, 0.f, 0.f};
            if (i & 1) {
#pragma unroll
                for (int k = 0; k < 7; k += 2)
                    s = f4fmap(c_g2[k], ci[((((i + k - 3) & 255) >> 1) << 5) + jb], s);
            } else {
#pragma unroll
                for (int k = 1; k < 7; k += 2)
                    s = f4fmap(c_g2[k], ci[((((i + k - 3) & 255) >> 1) << 5) + jb], s);
            }
            ((float4*)v)[rr * 32 + jb] = s;
        }
    }
    __syncthreads();
    {
        int jb = tid & 63, ib = tid >> 6;
        for (int rr = ib; rr < 32; rr += 4) {
            int i = rb * 32 + rr;
            const float* vr = v + rr * 128;
            float o[4];
#pragma unroll
            for (int m = 0; m < 4; ++m) {
                int j = 4 * jb + m;
                float s = 0.f;
                if (m & 1) {
#pragma unroll
                    for (int k = 0; k < 7; k += 2)
                        s = fmaf(c_g[k], vr[((j + k - 3) & 255) >> 1], s);
                } else {
#pragma unroll
                    for (int k = 1; k < 7; k += 2)
                        s = fmaf(c_g[k], vr[((j + k - 3) & 255) >> 1], s);
                }
                o[m] = s;
            }
            long fi = ((long)img << 14) + (i << 6) + jb;
            float4 xv = ((const float4*)x)[fi];
            ((float4*)bB)[fi] =
                make_float4(xv.x - o[0], xv.y - o[1], xv.z - o[2], xv.w - o[3]);
        }
    }
}

// ===== K_qp1: stage-D quincunx via diamond smem tile. bB(d) -> bP =========
__global__ void __launch_bounds__(256) k_qp1() {
    __shared__ __align__(16) float sm[64 * 68];   // 64 rows x 68-pitch
    int img = blockIdx.x >> 5;
    int tl = blockIdx.x & 31;
    int i0 = (tl >> 3) << 5, j0 = (tl & 7) << 5;
    int tid = threadIdx.x;
    const float4* di = (const float4*)bB + ((long)img << 14);
    int c0f = ((i0 + j0) & 255) >> 2;
    int rbase = i0 - j0 - 31;
#pragma unroll
    for (int r = 0; r < 4; ++r) {
        int p = tid + 256 * r;                  // 0..1023
        int u = p >> 4, vb = p & 15;
        int ru = (rbase + u) & 255;
        float4 val = di[(ru << 6) + ((c0f + vb) & 63)];
        *(float4*)&sm[u * 68 + 4 * vb] = val;
    }
    __syncthreads();
    int li = tid >> 3, lj0 = (tid & 7) << 2;
    float a[4], b[4];
#pragma unroll
    for (int m = 0; m < 4; ++m) {
        int lj = lj0 + m;
        int u = 31 + li - lj, vv = li + lj;
        a[m] = sm[u * 68 + vv];
        b[m] = sm[u * 68 + vv + 1];
    }
    long fi = ((long)img << 13) + ((i0 + li) << 6) + (j0 >> 2) + (tid & 7);
    ((float4*)bP)[fi]        = make_float4(a[0], a[1], a[2], a[3]);
    ((float4*)(bP + HM))[fi] = make_float4(b[0], b[1], b[2], b[3]);
}

// ===== K_D: packed-fma sliding-window qper_col vert f + streamed horiz f
//  + combine. (128,256) images, 16-row tiles. 256 img x 8 rowblocks ========
template<int OFF, int SRC>
__global__ void __launch_bounds__(256, 8) k_D() {
    __shared__ __align__(16) float t[16 * 256];   // 16 rows x 256 floats
    int rb = blockIdx.x & 7, img = blockIdx.x >> 3;
    int tid = threadIdx.x;
    const float2* s2 = (const float2*)(
        (SRC ? (const float4*)bA : (const float4*)(bP + HM)) + ((long)img << 13));
    // phase 1: vertical 12-tap f, 8 consecutive rows per thread, packed fma
    {
        int j2 = tid & 127, strip = tid >> 7;
        int r0 = rb * 16 + strip * 8;
        float2 acc[8];
#pragma unroll
        for (int q = 0; q < 8; ++q) acc[q] = make_float2(0.f, 0.f);
#pragma unroll
        for (int s = 0; s < 19; ++s) {
            int a = r0 - OFF + s;
            int row = a, c2 = j2;
            if (a < 0)        { row = a + 128; c2 = (j2 + 64) & 127; }
            else if (a > 127) { row = a - 128; c2 = (j2 + 64) & 127; }
            float2 v = s2[(row << 7) + c2];
#pragma unroll
            for (int q = 0; q < 8; ++q) {
                int k = s - q;
                if (k >= 0 && k < 12) acc[q] = f2fmap(c_f2[k], v, acc[q]);
            }
        }
#pragma unroll
        for (int q = 0; q < 8; ++q)
            ((float2*)t)[(strip * 8 + q) * 128 + j2] = acc[q];
    }
    __syncthreads();
    // phase 2: streamed horizontal f + combine (tap k = q - m - (8-OFF))
    {
        int jb = tid & 63, ib = tid >> 6;
        for (int rr = ib; rr < 16; rr += 4) {
            const float4* trow = (const float4*)t + rr * 64;
            float o0 = 0.f, o1 = 0.f, o2 = 0.f, o3 = 0.f;
#pragma unroll
            for (int s = 0; s < 5; ++s) {
                float4 v = trow[(jb - 2 + s + 64) & 63];
                float vv[4] = {v.x, v.y, v.z, v.w};
#pragma unroll
                for (int u = 0; u < 4; ++u) {
                    int q = 4 * s + u;
                    int k0 = q - (8 - OFF);
                    if (k0 >= 0 && k0 < 12) o0 = fmaf(c_f[k0], vv[u], o0);
                    int k1 = q - 1 - (8 - OFF);
                    if (k1 >= 0 && k1 < 12) o1 = fmaf(c_f[k1], vv[u], o1);
                    int k2 = q - 2 - (8 - OFF);
                    if (k2 >= 0 && k2 < 12) o2 = fmaf(c_f[k2], vv[u], o2);
                    int k3 = q - 3 - (8 - OFF);
                    if (k3 >= 0 && k3 < 12) o3 = fmaf(c_f[k3], vv[u], o3);
                }
            }
            int i = rb * 16 + rr;
            long fi = ((long)img << 13) + (i << 6) + jb;
            if (OFF == 6) {
                float4 p = ((const float4*)bP)[fi];
                ((float4*)bA)[fi] = make_float4((p.x - o0) * INV_SQ2,
                                                (p.y - o1) * INV_SQ2,
                                                (p.z - o2) * INV_SQ2,
                                                (p.w - o3) * INV_SQ2);
            } else {
                float4 p = ((const float4*)(bP + HM))[fi];
                ((float4*)(bA + HM))[fi] = make_float4(-SQ2 * p.x - o0,
                                                       -SQ2 * p.y - o1,
                                                       -SQ2 * p.z - o2,
                                                       -SQ2 * p.w - o3);
            }
        }
    }
}

// ===== K_qp2: stage-E quincunx via diamond smem tile. bA(z) -> bP ========
__global__ void __launch_bounds__(256) k_qp2() {
    __shared__ __align__(16) float sm[64 * 68];
    int img = blockIdx.x >> 4;                 // 512 imgs
    int tl = blockIdx.x & 15;
    int i0 = (tl >> 2) << 5, j0 = (tl & 3) << 5;
    int b = img >> 7, ch = img & 127;
    const float4* zi = (ch < 64)
        ? ((const float4*)bA        + ((long)((b << 6) + ch)      << 13))
        : ((const float4*)(bA + HM) + ((long)((b << 6) + ch - 64) << 13));
    int tid = threadIdx.x;
#pragma unroll
    for (int r = 0; r < 4; ++r) {
        int p = tid + 256 * r;
        int s = p >> 4, vb = p & 15;
        int aa = i0 + j0 + s;                  // < 256 always
        int row = aa & 127;
        int w = aa >> 7;
        int start = (j0 - i0 - 32 + (w << 7)) & 255;   // multiple of 4
        float4 val = zi[(row << 6) + (((start >> 2) + vb) & 63)];
        *(float4*)&sm[s * 68 + 4 * vb] = val;
    }
    __syncthreads();
    int li = tid >> 3, lj0 = (tid & 7) << 2;
    float a[4], bb[4];
#pragma unroll
    for (int m = 0; m < 4; ++m) {
        int lj = lj0 + m;
        int s = li + lj, vv = lj - li + 32;
        a[m]  = sm[s * 68 + vv];
        bb[m] = sm[(s + 1) * 68 + vv];
    }
    long fi = ((long)img << 12) + ((i0 + li) << 5) + (j0 >> 2) + (tid & 7);
    ((float4*)bP)[fi]        = make_float4(a[0], a[1], a[2], a[3]);
    ((float4*)(bP + HM))[fi] = make_float4(bb[0], bb[1], bb[2], bb[3]);
}

// ===== K_E: packed-fma sliding-window periodic vert f + streamed horiz f
//  + combine. (128,128) images, 32-row tiles. 512 img x 4 rowblocks ========
template<int OFF, int SRC>
__global__ void __launch_bounds__(256, 8) k_E(float* __restrict__ out) {
    __shared__ __align__(16) float t[32 * 128];   // 32 rows x 128 floats
    int rb = blockIdx.x & 3, img = blockIdx.x >> 2;
    int tid = threadIdx.x;
    int b = img >> 7, ch = img & 127;
    const float2* s2;
    if (SRC) {
        long base4 = (ch < 64)
            ? (2L * (SEG / 4) + ((long)((b << 6) + ch)      << 12))
            : (3L * (SEG / 4) + ((long)((b << 6) + ch - 64) << 12));
        s2 = (const float2*)((const float4*)out + base4);
    } else {
        s2 = (const float2*)((const float4*)(bP + HM) + ((long)img << 12));
    }
    // phase 1
    {
        int j2 = tid & 63, strip = tid >> 6;
        int r0 = rb * 32 + strip * 8;
        float2 acc[8];
#pragma unroll
        for (int q = 0; q < 8; ++q) acc[q] = make_float2(0.f, 0.f);
#pragma unroll
        for (int s = 0; s < 19; ++s) {
            int row = (r0 - OFF + s + 128) & 127;
            float2 v = s2[(row << 6) + j2];
#pragma unroll
            for (int q = 0; q < 8; ++q) {
                int k = s - q;
                if (k >= 0 && k < 12) acc[q] = f2fmap(c_f2[k], v, acc[q]);
            }
        }
#pragma unroll
        for (int q = 0; q < 8; ++q)
            ((float2*)t)[(strip * 8 + q) * 64 + j2] = acc[q];
    }
    __syncthreads();
    // phase 2: streamed horizontal f + combine
    {
        int jb = tid & 31, ib = tid >> 5;
        for (int rr = ib; rr < 32; rr += 8) {
            const float4* trow = (const float4*)t + rr * 32;
            float o0 = 0.f, o1 = 0.f, o2 = 0.f, o3 = 0.f;
#pragma unroll
            for (int s = 0; s < 5; ++s) {
                float4 v = trow[(jb - 2 + s + 32) & 31];
                float vv[4] = {v.x, v.y, v.z, v.w};
#pragma unroll
                for (int u = 0; u < 4; ++u) {
                    int q = 4 * s + u;
                    int k0 = q - (8 - OFF);
                    if (k0 >= 0 && k0 < 12) o0 = fmaf(c_f[k0], vv[u], o0);
                    int k1 = q - 1 - (8 - OFF);
                    if (k1 >= 0 && k1 < 12) o1 = fmaf(c_f[k1], vv[u], o1);
                    int k2 = q - 2 - (8 - OFF);
                    if (k2 >= 0 && k2 < 12) o2 = fmaf(c_f[k2], vv[u], o2);
                    int k3 = q - 3 - (8 - OFF);
                    if (k3 >= 0 && k3 < 12) o3 = fmaf(c_f[k3], vv[u], o3);
                }
            }
            int i = rb * 32 + rr;
            long fi = ((long)img << 12) + (i << 5) + jb;
            if (OFF == 6) {
                float4 p = ((const float4*)bP)[fi];
                float4 res = make_float4((p.x - o0) * INV_SQ2,
                                         (p.y - o1) * INV_SQ2,
                                         (p.z - o2) * INV_SQ2,
                                         (p.w - o3) * INV_SQ2);
                long base4 = (ch < 64)
                    ? (2L * (SEG / 4) + ((long)((b << 6) + ch)      << 12))
                    : (3L * (SEG / 4) + ((long)((b << 6) + ch - 64) << 12));
                ((float4*)out)[base4 + (i << 5) + jb] = res;
            } else {
                float4 p = ((const float4*)(bP + HM))[fi];
                float4 res = make_float4(-SQ2 * p.x - o0, -SQ2 * p.y - o1,
                                         -SQ2 * p.z - o2, -SQ2 * p.w - o3);
                long base4 = (ch < 64)
                    ? (1L * (SEG / 4) + ((long)((b << 6) + ch)      << 12))
                    : (4L * (SEG / 4) + ((long)((b << 6) + ch - 64) << 12));
                ((float4*)out)[base4 + (i << 5) + jb] = res;
            }
        }
    }
}

extern "C" void kernel_launch(void* const* d_in, const int* in_sizes, int n_in,
                              void* d_out, int out_size) {
    const float* x = (const float*)d_in[0];
    float* out = (float*)d_out;
    (void)in_sizes; (void)n_in; (void)out_size;

    const int T = 256;
    k_AB<<<1024, T>>>(x, out);        // c -> seg0
    k_C<<<2048, T>>>(out, x);         // d -> bB
    k_qp1<<<8192, T>>>();             // p0|p1 -> bP
    k_D<6, 0><<<2048, T>>>();         // y0a -> bA[0..HM)
    k_D<5, 1><<<2048, T>>>();         // y1a -> bA[HM..)
    k_qp2<<<8192, T>>>();             // p0b|p1b -> bP
    k_E<6, 0><<<2048, T>>>(out);      // e0 -> segs2/3
    k_E<5, 1><<<2048, T>>>(out);      // e1 -> segs1/4
}